// round 6
// baseline (speedup 1.0000x reference)
#include <cuda_runtime.h>
#include <cuda_fp16.h>
#include <cstdint>

// ---------------------------------------------------------------------------
// KAN layer as dense HMMA (mma.sync) f16 GEMM — tcgen05 unavailable because
// the harness PTX stage targets compute_103 (non-'a').
//
// out[b,j] = sum_{i,k} basis_k(tanh(x[b,i])) * C[j,i,k]
//   B=8192, I=1024, J=256, 13 basis slots padded to 16 -> K' = 16384.
// A[8192,16384] generated on the fly in SMEM (2 nonzeros per 16-slot group):
//   t = (clip(tanh(x))+1)*7.5, m = floor(t), u=(t-m)*S at slot m (m<=11),
//   v=S-u at slot m-1 (1<=m<=12), S = h/(h+eps).
// B'[256,16384] = fp16 coeffs (slot>=13 zero-padded).
// Split-K x2, fp32 partials, small reduce.
// ---------------------------------------------------------------------------

#define BATCH   8192
#define INF     1024
#define OUTF    256
#define KP      16384          // padded K
#define KSPLIT  2
#define KCTA    (KP / KSPLIT)  // 8192 halves = 512 features
#define BK      64             // k-chunk (4 features)
#define NCHUNK  (KCTA / BK)    // 128
#define MT      128            // CTA M tile
#define NT      256            // CTA N tile (full N)

// SMEM: A[2][128][64] halves (16KB ea), B[2][256][64] halves (32KB ea)
#define SA(s)   ((s) * 16384)
#define SB(s)   (32768 + (s) * 32768)
#define SM_TOTAL 98304

// -------------------------- device scratch ---------------------------------
__device__ __half g_Bh[OUTF * KP];                    // 8 MB fp16 coeffs
__device__ float  g_part[KSPLIT * BATCH * OUTF];      // 16 MB partials

// ----------------------------- helpers -------------------------------------
__device__ __forceinline__ uint32_t sw128(uint32_t o) { return o ^ ((o >> 3) & 0x70); }

__device__ __forceinline__ uint32_t s2u(const void* p) {
    uint32_t a;
    asm("{ .reg .u64 t; cvta.to.shared.u64 t, %1; cvt.u32.u64 %0, t; }" : "=r"(a) : "l"(p));
    return a;
}

__device__ __forceinline__ void cp16(uint32_t dst, const void* src) {
    asm volatile("cp.async.cg.shared.global [%0], [%1], 16;" :: "r"(dst), "l"(src));
}
__device__ __forceinline__ void cp_commit() { asm volatile("cp.async.commit_group;"); }
__device__ __forceinline__ void cp_wait0()  { asm volatile("cp.async.wait_group 0;"); }

__device__ __forceinline__ void ldmx4(uint32_t& r0, uint32_t& r1, uint32_t& r2,
                                      uint32_t& r3, uint32_t addr) {
    asm volatile("ldmatrix.sync.aligned.m8n8.x4.shared.b16 {%0,%1,%2,%3}, [%4];"
                 : "=r"(r0), "=r"(r1), "=r"(r2), "=r"(r3) : "r"(addr));
}

__device__ __forceinline__ void hmma(float* d, const uint32_t* a, uint32_t b0, uint32_t b1) {
    asm volatile(
        "mma.sync.aligned.m16n8k16.row.col.f32.f16.f16.f32 "
        "{%0,%1,%2,%3}, {%4,%5,%6,%7}, {%8,%9}, {%0,%1,%2,%3};"
        : "+f"(d[0]), "+f"(d[1]), "+f"(d[2]), "+f"(d[3])
        : "r"(a[0]), "r"(a[1]), "r"(a[2]), "r"(a[3]), "r"(b0), "r"(b1));
}

// ---------------------- kernel 1: coeff convert ----------------------------
// C [256][1024][13] f32 -> g_Bh [256][16384] fp16, slots 13..15 zero.
__global__ void __launch_bounds__(256) convB_kernel(const float* __restrict__ C) {
    int g = blockIdx.x * blockDim.x + threadIdx.x;   // one half2 each
    int n = g >> 13;            // row j (8192 half2 per row)
    int r = g & 8191;
    int k = r * 2;              // even half index
    int i = k >> 4;
    int s = k & 15;
    long base = (long)n * 13312 + (long)i * 13;
    float v0 = (s     < 13) ? C[base + s]     : 0.0f;
    float v1 = (s + 1 < 13) ? C[base + s + 1] : 0.0f;
    __half2 h = __floats2half2_rn(v0, v1);
    *(__half2*)(g_Bh + (size_t)n * KP + k) = h;
}

// ------------------------- kernel 2: main GEMM -----------------------------
// grid (64, 2): blockIdx.x = M tile, blockIdx.y = k-split
__global__ void __launch_bounds__(256, 1)
kan_mma_kernel(const float* __restrict__ x) {
    extern __shared__ char smem[];
    const uint32_t sb = s2u(smem);
    const int tid   = threadIdx.x;
    const int lane  = tid & 31;
    const int wid   = tid >> 5;
    const int warpM = wid & 1;          // 2 x 64 rows
    const int warpN = wid >> 1;         // 4 x 64 cols
    const int Mbase = blockIdx.x * MT;
    const int ks    = blockIdx.y;

    // --- per-thread producer roles ---
    // B copy: 2048 x 16B chunks -> id = tid + 256*j; n = id>>3, g = id&7
    // A gen : row = tid>>1 (0..127), p = tid&1 -> features 2p, 2p+1 of chunk
    const int arow = tid >> 1;
    const int ap   = tid & 1;
    const float* xrow = x + (size_t)(Mbase + arow) * INF + ks * (KCTA / 16);
    const __half* bsrc_base = g_Bh;     // [n][KP]

    const float S = 0.13333334f / (0.13333334f + 1e-8f);

    // --- ldmatrix per-lane address components ---
    const int rA = warpM * 64 + (lane & 7) + ((lane >> 3) & 1) * 8;  // + mf*16
    const int cA = (lane >> 4) * 16;                                  // byte
    const int rB = warpN * 64 + (lane & 7) + ((lane >> 4) & 1) * 8;  // + ng*16
    const int cB = ((lane >> 3) & 1) * 16;                            // byte

    float d[2][8][4];   // [mf? no: 4 mf] -- see below (use 4x8)
    // NOTE: warp tile 64x64 -> 4 m-frags x 8 n-frags
    float acc[4][8][4];
    #pragma unroll
    for (int mf = 0; mf < 4; mf++)
        #pragma unroll
        for (int nf = 0; nf < 8; nf++)
            #pragma unroll
            for (int q = 0; q < 4; q++) acc[mf][nf][q] = 0.0f;
    (void)d;

    // --------- producers for chunk t into stage st ----------
    auto loadB = [&](int t, int st) {
        const size_t koff = (size_t)ks * KCTA + (size_t)t * BK;
        #pragma unroll
        for (int j = 0; j < 8; j++) {
            int id = tid + 256 * j;
            int n  = id >> 3;
            int g  = id & 7;
            uint32_t dst = sb + SB(st) + sw128((uint32_t)(n * 128 + g * 16));
            cp16(dst, bsrc_base + (size_t)n * KP + koff + g * 8);
        }
        cp_commit();
    };

    auto genA = [&](int t, int st) {
        float2 xv = *(const float2*)(xrow + t * 4 + ap * 2);
        #pragma unroll
        for (int ff = 0; ff < 2; ff++) {
            float xin = ff ? xv.y : xv.x;
            float xc = tanhf(xin);
            xc = fminf(1.0f, fmaxf(-1.0f, xc));
            float tt = (xc + 1.0f) * 7.5f;
            int m = (int)tt; if (m > 15) m = 15;
            float u = (tt - (float)m) * S;
            uint32_t uh = (m <= 11)           ? (uint32_t)__half_as_ushort(__float2half_rn(u))     : 0u;
            uint32_t vh = (m >= 1 && m <= 12) ? (uint32_t)__half_as_ushort(__float2half_rn(S - u)) : 0u;
            uint32_t w[8];
            #pragma unroll
            for (int rr = 0; rr < 8; rr++) {
                int s0 = 2 * rr, s1 = 2 * rr + 1;
                uint32_t lo = (s0 == m) ? uh : ((s0 == m - 1) ? vh : 0u);
                uint32_t hi = (s1 == m) ? uh : ((s1 == m - 1) ? vh : 0u);
                w[rr] = lo | (hi << 16);
            }
            uint32_t base = (uint32_t)(arow * 128 + (ap * 2 + ff) * 32);
            *(uint4*)(smem + SA(st) + sw128(base))      = make_uint4(w[0], w[1], w[2], w[3]);
            *(uint4*)(smem + SA(st) + sw128(base + 16)) = make_uint4(w[4], w[5], w[6], w[7]);
        }
    };

    auto compute = [&](int st) {
        const uint32_t sA = sb + SA(st);
        const uint32_t sBB = sb + SB(st);
        #pragma unroll
        for (int kq = 0; kq < 4; kq++) {           // 4 k16 steps in BK=64
            uint32_t a[4][4], bb[4][4];
            #pragma unroll
            for (int mf = 0; mf < 4; mf++) {
                uint32_t addr = sA + sw128((uint32_t)((rA + mf * 16) * 128 + kq * 32 + cA));
                ldmx4(a[mf][0], a[mf][1], a[mf][2], a[mf][3], addr);
            }
            #pragma unroll
            for (int ng = 0; ng < 4; ng++) {
                uint32_t addr = sBB + sw128((uint32_t)((rB + ng * 16) * 128 + kq * 32 + cB));
                ldmx4(bb[ng][0], bb[ng][1], bb[ng][2], bb[ng][3], addr);
            }
            #pragma unroll
            for (int mf = 0; mf < 4; mf++)
                #pragma unroll
                for (int nf = 0; nf < 8; nf++)
                    hmma(acc[mf][nf], a[mf],
                         bb[nf >> 1][(nf & 1) * 2], bb[nf >> 1][(nf & 1) * 2 + 1]);
        }
    };

    // ------------------------------ pipeline -------------------------------
    loadB(0, 0);
    genA(0, 0);
    cp_wait0();
    __syncthreads();

    for (int t = 0; t < NCHUNK; t++) {
        int cur = t & 1;
        if (t + 1 < NCHUNK) {
            loadB(t + 1, cur ^ 1);
            genA(t + 1, cur ^ 1);
        }
        compute(cur);
        cp_wait0();
        __syncthreads();
    }

    // ------------------------------ epilogue -------------------------------
    float* outp = g_part + (size_t)ks * BATCH * OUTF;
    const int r0 = Mbase + warpM * 64 + (lane >> 2);
    const int c0 = warpN * 64 + (lane & 3) * 2;
    #pragma unroll
    for (int mf = 0; mf < 4; mf++) {
        #pragma unroll
        for (int nf = 0; nf < 8; nf++) {
            int row = r0 + mf * 16;
            int col = c0 + nf * 8;
            *(float2*)(outp + (size_t)row * OUTF + col) =
                make_float2(acc[mf][nf][0], acc[mf][nf][1]);
            *(float2*)(outp + (size_t)(row + 8) * OUTF + col) =
                make_float2(acc[mf][nf][2], acc[mf][nf][3]);
        }
    }
}

// ------------------------ kernel 3: split-K reduce -------------------------
__global__ void __launch_bounds__(512) reduceK_kernel(float* __restrict__ out) {
    int g = blockIdx.x * blockDim.x + threadIdx.x;   // float4 units
    const float4* p = (const float4*)g_part;
    const int STRIDE = (BATCH * OUTF) / 4;
    float4 a = p[g];
    float4 b = p[g + STRIDE];
    ((float4*)out)[g] = make_float4(a.x + b.x, a.y + b.y, a.z + b.z, a.w + b.w);
}

// ------------------------------- launch ------------------------------------
extern "C" void kernel_launch(void* const* d_in, const int* in_sizes, int n_in,
                              void* d_out, int out_size) {
    const float* x = (const float*)d_in[0];
    const float* C = (const float*)d_in[1];
    // knots input unused: grid is the analytic linspace(-1,1,16)

    cudaFuncSetAttribute(kan_mma_kernel,
                         cudaFuncAttributeMaxDynamicSharedMemorySize, SM_TOTAL);

    convB_kernel<<<8192, 256>>>(C);
    kan_mma_kernel<<<dim3(64, KSPLIT), 256, SM_TOTAL>>>(x);
    reduceK_kernel<<<1024, 512>>>((float*)d_out);
}

// round 7
// speedup vs baseline: 1.1131x; 1.1131x over previous
#include <cuda_runtime.h>
#include <cuda_fp16.h>
#include <cstdint>

// ---------------------------------------------------------------------------
// KAN layer as dense HMMA (mma.sync) f16 GEMM (tcgen05 blocked: harness PTX
// targets compute_103 non-'a').
//
// out[b,j] = sum_{i,k} basis_k(tanh(x[b,i])) * C[j,i,k]
//   B=8192, I=1024, J=256, 13 basis slots padded to 16 -> K' = 16384.
//
// prep:  per (b,i) precompute the 2 nonzero halves packed as SMEM words:
//        W0 at word q, W1 at word q+1 of the feature's 8-word (16-half) stripe.
// main:  A tile built from (W0,W1,q) with 4 STS per feature, interleaved into
//        the MMA k-step loop; B streamed via cp.async. BK=128, double buffer.
// Split-K x2, fp32 partials, reduce.
// ---------------------------------------------------------------------------

#define BATCH   8192
#define INF     1024
#define OUTF    256
#define KP      16384          // padded K
#define KSPLIT  2
#define KCTA    (KP / KSPLIT)  // 8192 halves = 512 features
#define BK      128            // k-chunk (8 features)
#define NCHUNK  (KCTA / BK)    // 64
#define MT      128            // CTA M tile
#define NT      256            // CTA N tile

// SMEM: A[2][2kh][128][64]h (32KB/stage), B[2][2kh][256][64]h (64KB/stage)
#define SA(s)   ((s) * 32768)
#define SB(s)   (65536 + (s) * 65536)
#define SM_TOTAL 196608

// -------------------------- device scratch ---------------------------------
__device__ __half g_Bh[OUTF * KP];                 // 8 MB fp16 coeffs
__device__ uint2  g_W[BATCH * INF];                // 64 MB packed hat words
__device__ float  g_part[KSPLIT * BATCH * OUTF];   // 16 MB partials

// ----------------------------- helpers -------------------------------------
__device__ __forceinline__ uint32_t sw128(uint32_t o) { return o ^ ((o >> 3) & 0x70); }

__device__ __forceinline__ uint32_t s2u(const void* p) {
    uint32_t a;
    asm("{ .reg .u64 t; cvta.to.shared.u64 t, %1; cvt.u32.u64 %0, t; }" : "=r"(a) : "l"(p));
    return a;
}

__device__ __forceinline__ void cp16(uint32_t dst, const void* src) {
    asm volatile("cp.async.cg.shared.global [%0], [%1], 16;" :: "r"(dst), "l"(src));
}
__device__ __forceinline__ void cp_commit() { asm volatile("cp.async.commit_group;"); }
__device__ __forceinline__ void cp_wait0()  { asm volatile("cp.async.wait_group 0;"); }

__device__ __forceinline__ void ldmx4(uint32_t& r0, uint32_t& r1, uint32_t& r2,
                                      uint32_t& r3, uint32_t addr) {
    asm volatile("ldmatrix.sync.aligned.m8n8.x4.shared.b16 {%0,%1,%2,%3}, [%4];"
                 : "=r"(r0), "=r"(r1), "=r"(r2), "=r"(r3) : "r"(addr));
}

__device__ __forceinline__ void hmma(float* d, const uint32_t* a, uint32_t b0, uint32_t b1) {
    asm volatile(
        "mma.sync.aligned.m16n8k16.row.col.f32.f16.f16.f32 "
        "{%0,%1,%2,%3}, {%4,%5,%6,%7}, {%8,%9}, {%0,%1,%2,%3};"
        : "+f"(d[0]), "+f"(d[1]), "+f"(d[2]), "+f"(d[3])
        : "r"(a[0]), "r"(a[1]), "r"(a[2]), "r"(a[3]), "r"(b0), "r"(b1));
}

// ---------------------- kernel 0: hat precompute ---------------------------
// x [8192][1024] f32 -> g_W uint2 {W0, W1(16b)|q<<16} per element.
// Same math as the validated R5 kernel: t=(clip(tanh x)+1)*7.5, m=floor,
// u=(t-m)*S; uh at slot m (m<=11), vh=S-u at slot m-1 (1<=m<=12).
// Slot pair lives in words q, q+1 of the 8-u32 stripe (2 halves per word).
__global__ void __launch_bounds__(256) prep_kernel(const float* __restrict__ x) {
    const float S = 0.13333334f / (0.13333334f + 1e-8f);
    int g = blockIdx.x * blockDim.x + threadIdx.x;     // 4 elems each
    float4 xv = ((const float4*)x)[g];
    uint2 o[4];
    #pragma unroll
    for (int e = 0; e < 4; e++) {
        float v = (e == 0) ? xv.x : (e == 1) ? xv.y : (e == 2) ? xv.z : xv.w;
        float xc = tanhf(v);
        xc = fminf(1.0f, fmaxf(-1.0f, xc));
        float tt = (xc + 1.0f) * 7.5f;
        int m = (int)tt; if (m > 15) m = 15;
        float u = (tt - (float)m) * S;
        uint32_t uh = (m <= 11)           ? (uint32_t)__half_as_ushort(__float2half_rn(u))     : 0u;
        uint32_t vh = (m >= 1 && m <= 12) ? (uint32_t)__half_as_ushort(__float2half_rn(S - u)) : 0u;
        uint32_t W0, W1, q;
        if (m >= 13)      { W0 = 0; W1 = 0; q = 0; }              // all masked
        else if (m == 0)  { W0 = uh; W1 = 0; q = 0; }             // uh at lo of word 0
        else if (m & 1)   { W0 = vh | (uh << 16); W1 = 0; q = (uint32_t)(m >> 1); }
        else              { W0 = vh << 16; W1 = uh; q = (uint32_t)((m >> 1) - 1); }
        o[e] = make_uint2(W0, W1 | (q << 16));
    }
    uint4* dst = (uint4*)(g_W + (size_t)g * 4);
    dst[0] = make_uint4(o[0].x, o[0].y, o[1].x, o[1].y);
    dst[1] = make_uint4(o[2].x, o[2].y, o[3].x, o[3].y);
}

// ---------------------- kernel 1: coeff convert ----------------------------
// C [256][1024][13] f32 -> g_Bh [256][16384] fp16, slots 13..15 zero.
__global__ void __launch_bounds__(256) convB_kernel(const float* __restrict__ C) {
    int g = blockIdx.x * blockDim.x + threadIdx.x;   // one half2 each
    int n = g >> 13;
    int r = g & 8191;
    int k = r * 2;
    int i = k >> 4;
    int s = k & 15;
    long base = (long)n * 13312 + (long)i * 13;
    float v0 = (s     < 13) ? C[base + s]     : 0.0f;
    float v1 = (s + 1 < 13) ? C[base + s + 1] : 0.0f;
    __half2 h = __floats2half2_rn(v0, v1);
    *(__half2*)(g_Bh + (size_t)n * KP + k) = h;
}

// ------------------------- kernel 2: main GEMM -----------------------------
// grid (64, 2): blockIdx.x = M tile, blockIdx.y = k-split
__global__ void __launch_bounds__(256, 1)
kan_mma_kernel() {
    extern __shared__ char smem[];
    const uint32_t sb = s2u(smem);
    const int tid   = threadIdx.x;
    const int lane  = tid & 31;
    const int wid   = tid >> 5;
    const int warpM = wid & 1;          // 2 x 64 rows
    const int warpN = wid >> 1;         // 4 x 64 cols
    const int Mbase = blockIdx.x * MT;
    const int ks    = blockIdx.y;

    // producer roles: 2 threads per row; ap selects features ap*4..ap*4+3
    const int arow = tid >> 1;
    const int ap   = tid & 1;
    const uint2* wsrc = g_W + (size_t)(Mbase + arow) * INF + ks * (KCTA / 16) + ap * 4;

    // ldmatrix per-lane address components (validated layout, unchanged)
    const int rA = warpM * 64 + (lane & 7) + ((lane >> 3) & 1) * 8;
    const int cA = (lane >> 4) * 16;
    const int rB = warpN * 64 + (lane & 7) + ((lane >> 4) & 1) * 8;
    const int cB = ((lane >> 3) & 1) * 16;

    float acc[4][8][4];
    #pragma unroll
    for (int mf = 0; mf < 4; mf++)
        #pragma unroll
        for (int nf = 0; nf < 8; nf++)
            #pragma unroll
            for (int q = 0; q < 4; q++) acc[mf][nf][q] = 0.0f;

    // ---- producer pieces ----
    // load packed words for chunk t (4 features -> 2 uint4)
    auto loadW = [&](int t, uint2* w) {
        const uint4* p = (const uint4*)(wsrc + (size_t)t * 8);
        uint4 r0 = p[0], r1 = p[1];
        w[0] = make_uint2(r0.x, r0.y); w[1] = make_uint2(r0.z, r0.w);
        w[2] = make_uint2(r1.x, r1.y); w[3] = make_uint2(r1.z, r1.w);
    };

    // write one feature's 16-half stripe: zero 32B then place W0,W1 at words q,q+1
    auto putA = [&](int st, int fl, uint2 wv) {
        int f = ap * 4 + fl;
        uint32_t As = sb + SA(st) + (f >> 2) * 16384;
        uint32_t base = (uint32_t)(arow * 128 + (f & 3) * 32);
        uint32_t a0 = As + sw128(base);
        uint32_t a1 = As + sw128(base + 16);
        asm volatile("st.shared.v4.b32 [%0], {%1,%1,%1,%1};" :: "r"(a0), "r"(0u) : "memory");
        asm volatile("st.shared.v4.b32 [%0], {%1,%1,%1,%1};" :: "r"(a1), "r"(0u) : "memory");
        uint32_t W0 = wv.x;
        uint32_t W1 = wv.y & 0xFFFFu;
        uint32_t q  = wv.y >> 16;
        uint32_t o0 = base + q * 4;
        uint32_t o1 = o0 + 4;
        asm volatile("st.shared.b32 [%0], %1;" :: "r"(As + sw128(o0)), "r"(W0) : "memory");
        asm volatile("st.shared.b32 [%0], %1;" :: "r"(As + sw128(o1)), "r"(W1) : "memory");
    };

    // 2 cp.async (of 16 total) for chunk t's B tile, slice s in 0..7
    auto cpB = [&](int t, int st, int s) {
        const size_t koff = (size_t)ks * KCTA + (size_t)t * BK;
        #pragma unroll
        for (int jj = 0; jj < 2; jj++) {
            int id  = (s * 2 + jj) * 256 + tid;       // 0..4095
            int kh  = id >> 11;
            int rem = id & 2047;
            int n   = rem >> 3;
            int g   = rem & 7;
            uint32_t dst = sb + SB(st) + kh * 32768 + sw128((uint32_t)(n * 128 + g * 16));
            cp16(dst, g_Bh + (size_t)n * KP + koff + kh * 64 + g * 8);
        }
    };

    // ------------------------------ prologue --------------------------------
    {
        uint2 w0[4];
        loadW(0, w0);
        #pragma unroll
        for (int fl = 0; fl < 4; fl++) putA(0, fl, w0[fl]);
        #pragma unroll
        for (int s = 0; s < 8; s++) cpB(0, 0, s);
        cp_commit();
    }
    uint2 wcur[4];
    loadW(1, wcur);
    cp_wait0();
    __syncthreads();

    // ------------------------------ main loop -------------------------------
    for (int t = 0; t < NCHUNK; t++) {
        const int cur = t & 1, nxt = cur ^ 1;
        const bool hasnext = (t + 1 < NCHUNK);
        uint2 wnext[4];

        #pragma unroll
        for (int kq = 0; kq < 8; kq++) {
            // producer slice for chunk t+1 (fills stage nxt)
            if (hasnext) {
                if (kq == 0) {
                    if (t + 2 < NCHUNK) loadW(t + 2, wnext);
                } else if (kq <= 4) {
                    putA(nxt, kq - 1, wcur[kq - 1]);
                }
                cpB(t + 1, nxt, kq);
                if (kq == 7) cp_commit();
            }

            // compute (stage cur, k16 step kq)
            const int kh = kq >> 2, kr = kq & 3;
            const uint32_t sA  = sb + SA(cur) + kh * 16384;
            const uint32_t sBB = sb + SB(cur) + kh * 32768;
            uint32_t a[4][4], bb[4][4];
            #pragma unroll
            for (int mf = 0; mf < 4; mf++) {
                uint32_t addr = sA + sw128((uint32_t)((rA + mf * 16) * 128 + kr * 32 + cA));
                ldmx4(a[mf][0], a[mf][1], a[mf][2], a[mf][3], addr);
            }
            #pragma unroll
            for (int ng = 0; ng < 4; ng++) {
                uint32_t addr = sBB + sw128((uint32_t)((rB + ng * 16) * 128 + kr * 32 + cB));
                ldmx4(bb[ng][0], bb[ng][1], bb[ng][2], bb[ng][3], addr);
            }
            #pragma unroll
            for (int mf = 0; mf < 4; mf++)
                #pragma unroll
                for (int nf = 0; nf < 8; nf++)
                    hmma(acc[mf][nf], a[mf],
                         bb[nf >> 1][(nf & 1) * 2], bb[nf >> 1][(nf & 1) * 2 + 1]);
        }

        if (hasnext) {
            #pragma unroll
            for (int fl = 0; fl < 4; fl++) wcur[fl] = wnext[fl];
        }
        cp_wait0();
        __syncthreads();
    }

    // ------------------------------ epilogue -------------------------------
    float* outp = g_part + (size_t)ks * BATCH * OUTF;
    const int r0 = Mbase + warpM * 64 + (lane >> 2);
    const int c0 = warpN * 64 + (lane & 3) * 2;
    #pragma unroll
    for (int mf = 0; mf < 4; mf++) {
        #pragma unroll
        for (int nf = 0; nf < 8; nf++) {
            int row = r0 + mf * 16;
            int col = c0 + nf * 8;
            *(float2*)(outp + (size_t)row * OUTF + col) =
                make_float2(acc[mf][nf][0], acc[mf][nf][1]);
            *(float2*)(outp + (size_t)(row + 8) * OUTF + col) =
                make_float2(acc[mf][nf][2], acc[mf][nf][3]);
        }
    }
}

// ------------------------ kernel 3: split-K reduce -------------------------
__global__ void __launch_bounds__(512) reduceK_kernel(float* __restrict__ out) {
    int g = blockIdx.x * blockDim.x + threadIdx.x;   // float4 units
    const float4* p = (const float4*)g_part;
    const int STRIDE = (BATCH * OUTF) / 4;
    float4 a = p[g];
    float4 b = p[g + STRIDE];
    ((float4*)out)[g] = make_float4(a.x + b.x, a.y + b.y, a.z + b.z, a.w + b.w);
}

// ------------------------------- launch ------------------------------------
extern "C" void kernel_launch(void* const* d_in, const int* in_sizes, int n_in,
                              void* d_out, int out_size) {
    const float* x = (const float*)d_in[0];
    const float* C = (const float*)d_in[1];
    // knots input unused: grid is the analytic linspace(-1,1,16)

    cudaFuncSetAttribute(kan_mma_kernel,
                         cudaFuncAttributeMaxDynamicSharedMemorySize, SM_TOTAL);

    prep_kernel<<<8192, 256>>>(x);
    convB_kernel<<<8192, 256>>>(C);
    kan_mma_kernel<<<dim3(64, KSPLIT), 256, SM_TOTAL>>>();
    reduceK_kernel<<<1024, 512>>>((float*)d_out);
}